// round 1
// baseline (speedup 1.0000x reference)
#include <cuda_runtime.h>
#include <cuda_bf16.h>
#include <math.h>

#define NN 100000
#define EE 3200000
#define NHID 256
#define NCLASS 16
#define SCAN_BLK 1024
#define NSCANBLK ((NN + SCAN_BLK - 1) / SCAN_BLK)   // 98

// ---------------- scratch (static device globals; no runtime allocation) ----
__device__ float g_S[(size_t)NN * NHID];   // GEMM output / spmm input
__device__ float g_A[(size_t)NN * NHID];   // ping
__device__ float g_B[(size_t)NN * NHID];   // pong
__device__ int   g_col[EE];
__device__ float g_val[EE];
__device__ int   g_rowptr[NN + 1];
__device__ int   g_cursor[NN];             // counts, then scatter cursors
__device__ int   g_blocksums[SCAN_BLK];

// ---------------- CSR build --------------------------------------------------
__global__ void k_zero_cnt() {
    int i = blockIdx.x * blockDim.x + threadIdx.x;
    if (i < NN) g_cursor[i] = 0;
}

__global__ void k_hist(const int* __restrict__ row) {
    int e = blockIdx.x * blockDim.x + threadIdx.x;
    if (e < EE) atomicAdd(&g_cursor[row[e]], 1);
}

__global__ void k_scan1() {
    __shared__ int s[SCAN_BLK];
    int t = threadIdx.x;
    int gid = blockIdx.x * SCAN_BLK + t;
    s[t] = (gid < NN) ? g_cursor[gid] : 0;
    for (int d = 1; d < SCAN_BLK; d <<= 1) {
        __syncthreads();
        int u = (t >= d) ? s[t - d] : 0;
        __syncthreads();
        s[t] += u;
    }
    __syncthreads();
    if (gid < NN) g_rowptr[gid + 1] = s[t];
    if (t == SCAN_BLK - 1) g_blocksums[blockIdx.x] = s[t];
}

__global__ void k_scan2() {
    __shared__ int s[128];
    int t = threadIdx.x;
    s[t] = (t < NSCANBLK) ? g_blocksums[t] : 0;
    for (int d = 1; d < 128; d <<= 1) {
        __syncthreads();
        int u = (t >= d) ? s[t - d] : 0;
        __syncthreads();
        s[t] += u;
    }
    __syncthreads();
    if (t < NSCANBLK) g_blocksums[t] = s[t];
}

__global__ void k_scan3() {
    int i = blockIdx.x * blockDim.x + threadIdx.x;
    if (i < NN) {
        int b = i >> 10;
        int off = b ? g_blocksums[b - 1] : 0;
        g_rowptr[i + 1] += off;
        if (i == 0) g_rowptr[0] = 0;
    }
}

__global__ void k_cursor_init() {
    int i = blockIdx.x * blockDim.x + threadIdx.x;
    if (i < NN) g_cursor[i] = g_rowptr[i];
}

__global__ void k_scatter(const int* __restrict__ row, const int* __restrict__ col,
                          const float* __restrict__ val) {
    int e = blockIdx.x * blockDim.x + threadIdx.x;
    if (e < EE) {
        int r = row[e];
        int p = atomicAdd(&g_cursor[r], 1);
        g_col[p] = col[e];
        g_val[p] = val[e];
    }
}

// ---------------- dense GEMM: C[M,256] = A[M,K] @ B[K,256] ------------------
// 64x64 block tile, BK=16, 256 threads, 4x4 microtile.
__global__ void k_gemm(const float* __restrict__ A, const float* __restrict__ B,
                       float* __restrict__ C, int M, int K) {
    __shared__ float As[16][65];
    __shared__ float Bs[16][64];
    int tid = threadIdx.x;
    int row0 = blockIdx.x * 64;
    int col0 = blockIdx.y * 64;
    int tx = tid & 15, ty = tid >> 4;

    int aRow = tid >> 2;          // 0..63
    int aCol = (tid & 3) * 4;     // 0,4,8,12
    int bRow = tid >> 4;          // 0..15
    int bCol = (tid & 15) * 4;    // 0..60

    float acc[4][4] = {};

    for (int k0 = 0; k0 < K; k0 += 16) {
        float4 av = make_float4(0.f, 0.f, 0.f, 0.f);
        int gr = row0 + aRow;
        if (gr < M) av = *(const float4*)(A + (size_t)gr * K + k0 + aCol);
        As[aCol + 0][aRow] = av.x;
        As[aCol + 1][aRow] = av.y;
        As[aCol + 2][aRow] = av.z;
        As[aCol + 3][aRow] = av.w;
        float4 bv = *(const float4*)(B + (size_t)(k0 + bRow) * NHID + col0 + bCol);
        *(float4*)&Bs[bRow][bCol] = bv;
        __syncthreads();
#pragma unroll
        for (int kk = 0; kk < 16; kk++) {
            float ra[4], rb[4];
#pragma unroll
            for (int i = 0; i < 4; i++) ra[i] = As[kk][ty * 4 + i];
#pragma unroll
            for (int j = 0; j < 4; j++) rb[j] = Bs[kk][tx * 4 + j];
#pragma unroll
            for (int i = 0; i < 4; i++)
#pragma unroll
                for (int j = 0; j < 4; j++) acc[i][j] += ra[i] * rb[j];
        }
        __syncthreads();
    }
#pragma unroll
    for (int i = 0; i < 4; i++) {
        int gr = row0 + ty * 4 + i;
        if (gr < M) {
            float4 v = make_float4(acc[i][0], acc[i][1], acc[i][2], acc[i][3]);
            *(float4*)(C + (size_t)gr * NHID + col0 + tx * 4) = v;
        }
    }
}

// ---------------- SpMM (CSR) + bias + relu ----------------------------------
// One warp per destination node; 256 fp32 columns = 2 float4 per lane.
__global__ void k_spmm_bias_relu(const float* __restrict__ S,
                                 const float* __restrict__ bias,
                                 float* __restrict__ out) {
    int w = (blockIdx.x * blockDim.x + threadIdx.x) >> 5;
    if (w >= NN) return;
    int lane = threadIdx.x & 31;
    const float4* S4 = (const float4*)S;

    float4 a0 = make_float4(0.f, 0.f, 0.f, 0.f);
    float4 a1 = make_float4(0.f, 0.f, 0.f, 0.f);

    int s = g_rowptr[w], e = g_rowptr[w + 1];
    for (int base = s; base < e; base += 32) {
        int idx = base + lane;
        int c = 0;
        float v = 0.f;
        if (idx < e) { c = g_col[idx]; v = g_val[idx]; }
        int m = min(32, e - base);
        if (m == 32) {
#pragma unroll 8
            for (int j = 0; j < 32; j++) {
                int cj = __shfl_sync(0xffffffffu, c, j);
                float vj = __shfl_sync(0xffffffffu, v, j);
                float4 p0 = S4[(size_t)cj * 64 + lane];
                float4 p1 = S4[(size_t)cj * 64 + 32 + lane];
                a0.x += vj * p0.x; a0.y += vj * p0.y; a0.z += vj * p0.z; a0.w += vj * p0.w;
                a1.x += vj * p1.x; a1.y += vj * p1.y; a1.z += vj * p1.z; a1.w += vj * p1.w;
            }
        } else {
            for (int j = 0; j < m; j++) {
                int cj = __shfl_sync(0xffffffffu, c, j);
                float vj = __shfl_sync(0xffffffffu, v, j);
                float4 p0 = S4[(size_t)cj * 64 + lane];
                float4 p1 = S4[(size_t)cj * 64 + 32 + lane];
                a0.x += vj * p0.x; a0.y += vj * p0.y; a0.z += vj * p0.z; a0.w += vj * p0.w;
                a1.x += vj * p1.x; a1.y += vj * p1.y; a1.z += vj * p1.z; a1.w += vj * p1.w;
            }
        }
    }
    float4 b0 = ((const float4*)bias)[lane];
    float4 b1 = ((const float4*)bias)[32 + lane];
    a0.x = fmaxf(a0.x + b0.x, 0.f); a0.y = fmaxf(a0.y + b0.y, 0.f);
    a0.z = fmaxf(a0.z + b0.z, 0.f); a0.w = fmaxf(a0.w + b0.w, 0.f);
    a1.x = fmaxf(a1.x + b1.x, 0.f); a1.y = fmaxf(a1.y + b1.y, 0.f);
    a1.z = fmaxf(a1.z + b1.z, 0.f); a1.w = fmaxf(a1.w + b1.w, 0.f);
    ((float4*)out)[(size_t)w * 64 + lane] = a0;
    ((float4*)out)[(size_t)w * 64 + 32 + lane] = a1;
}

// ---------------- fused FC + log_softmax ------------------------------------
// One warp per row; lanes 0..15 each own one class.
__global__ void k_fc_lsm(const float* __restrict__ H, const float* __restrict__ fw,
                         const float* __restrict__ fb, float* __restrict__ out) {
    __shared__ float sh[8][NHID];
    int wIn = threadIdx.x >> 5;
    int lane = threadIdx.x & 31;
    int i = blockIdx.x * 8 + wIn;
    if (i >= NN) return;
#pragma unroll
    for (int j = 0; j < 8; j++)
        sh[wIn][j * 32 + lane] = H[(size_t)i * NHID + j * 32 + lane];
    __syncwarp();
    if (lane < NCLASS) {
        float acc = fb[lane];
#pragma unroll 8
        for (int k = 0; k < NHID; k++) acc += sh[wIn][k] * fw[k * NCLASS + lane];
        float mx = acc;
#pragma unroll
        for (int o = 8; o; o >>= 1) mx = fmaxf(mx, __shfl_xor_sync(0xffffu, mx, o));
        float ex = expf(acc - mx);
        float sm = ex;
#pragma unroll
        for (int o = 8; o; o >>= 1) sm += __shfl_xor_sync(0xffffu, sm, o);
        out[(size_t)i * NCLASS + lane] = (acc - mx) - logf(sm);
    }
}

// ---------------- launch -----------------------------------------------------
extern "C" void kernel_launch(void* const* d_in, const int* in_sizes, int n_in,
                              void* d_out, int out_size) {
    const float* x       = (const float*)d_in[0];
    const float* adj_val = (const float*)d_in[1];
    const float* w1 = (const float*)d_in[2];
    const float* b1 = (const float*)d_in[3];
    const float* w2 = (const float*)d_in[4];
    const float* b2 = (const float*)d_in[5];
    const float* w3 = (const float*)d_in[6];
    const float* b3 = (const float*)d_in[7];
    const float* w4 = (const float*)d_in[8];
    const float* b4 = (const float*)d_in[9];
    const float* fc_w = (const float*)d_in[10];
    const float* fc_b = (const float*)d_in[11];
    const int* adj_row = (const int*)d_in[12];
    const int* adj_col = (const int*)d_in[13];
    float* out = (float*)d_out;

    float* S; cudaGetSymbolAddress((void**)&S, g_S);
    float* A; cudaGetSymbolAddress((void**)&A, g_A);
    float* B; cudaGetSymbolAddress((void**)&B, g_B);

    const int nThreads = 256;
    int nBlkN = (NN + nThreads - 1) / nThreads;
    int nBlkE = (EE + nThreads - 1) / nThreads;

    // --- build CSR (once per launch, reused by all 4 spmm) ---
    k_zero_cnt<<<nBlkN, nThreads>>>();
    k_hist<<<nBlkE, nThreads>>>(adj_row);
    k_scan1<<<NSCANBLK, SCAN_BLK>>>();
    k_scan2<<<1, 128>>>();
    k_scan3<<<nBlkN, nThreads>>>();
    k_cursor_init<<<nBlkN, nThreads>>>();
    k_scatter<<<nBlkE, nThreads>>>(adj_row, adj_col, adj_val);

    dim3 gemmGrid((NN + 63) / 64, NHID / 64);
    int spmmBlocks = (NN * 32 + nThreads - 1) / nThreads;

    // layer 1: x[N,128] @ w1 -> S; spmm(S)+b1 relu -> A
    k_gemm<<<gemmGrid, nThreads>>>(x, w1, S, NN, 128);
    k_spmm_bias_relu<<<spmmBlocks, nThreads>>>(S, b1, A);
    // layer 2
    k_gemm<<<gemmGrid, nThreads>>>(A, w2, S, NN, NHID);
    k_spmm_bias_relu<<<spmmBlocks, nThreads>>>(S, b2, B);
    // layer 3
    k_gemm<<<gemmGrid, nThreads>>>(B, w3, S, NN, NHID);
    k_spmm_bias_relu<<<spmmBlocks, nThreads>>>(S, b3, A);
    // layer 4
    k_gemm<<<gemmGrid, nThreads>>>(A, w4, S, NN, NHID);
    k_spmm_bias_relu<<<spmmBlocks, nThreads>>>(S, b4, B);
    // FC + log_softmax
    int fcBlocks = (NN + 7) / 8;
    k_fc_lsm<<<fcBlocks, nThreads>>>(B, fc_w, fc_b, out);
}

// round 3
// speedup vs baseline: 1.5294x; 1.5294x over previous
#include <cuda_runtime.h>
#include <cuda_bf16.h>
#include <math.h>
#include <stdint.h>

#define NN 100000
#define EE 3200000
#define NHID 256
#define NCLASS 16
#define SCAN_BLK 1024
#define NSCANBLK ((NN + SCAN_BLK - 1) / SCAN_BLK)   // 98

// ---------------- scratch (static device globals) ---------------------------
__device__ float g_S[(size_t)NN * NHID];   // GEMM output / spmm input
__device__ float g_A[(size_t)NN * NHID];   // ping
__device__ float g_B[(size_t)NN * NHID];   // pong
__device__ float g_X[(size_t)NN * 128];    // tf32-rounded input x
__device__ int   g_col[EE];
__device__ float g_val[EE];
__device__ int   g_rowptr[NN + 1];
__device__ int   g_cursor[NN];
__device__ int   g_blocksums[SCAN_BLK];
__device__ float g_Wq1[256 * 128];         // weights: [n][k] K-major, tf32-rounded
__device__ float g_Wq2[256 * 256];
__device__ float g_Wq3[256 * 256];
__device__ float g_Wq4[256 * 256];

__device__ __forceinline__ float f2tf32f(float x) {
    uint32_t r;
    asm("cvt.rna.tf32.f32 %0, %1;" : "=r"(r) : "f"(x));
    return __uint_as_float(r);
}

__device__ __forceinline__ uint32_t smem_u32(const void* p) {
    uint32_t a;
    asm("{ .reg .u64 t; cvta.to.shared.u64 t, %1; cvt.u32.u64 %0, t; }"
        : "=r"(a) : "l"(p));
    return a;
}

__device__ __forceinline__ void cpasync16(uint32_t dst, const void* src) {
    asm volatile("cp.async.ca.shared.global [%0], [%1], 16;" :: "r"(dst), "l"(src));
}

// ---------------- prep: round x to tf32; transpose+round weights ------------
__global__ void k_prep(const float* __restrict__ x,
                       const float* __restrict__ w1, const float* __restrict__ w2,
                       const float* __restrict__ w3, const float* __restrict__ w4) {
    long long i = (long long)blockIdx.x * blockDim.x + threadIdx.x;
    const long long NW1 = 256 * 128;
    const long long NW = 256 * 256;
    if (i < NW1) {
        int n = (int)(i / 128), k = (int)(i % 128);
        g_Wq1[i] = f2tf32f(w1[k * 256 + n]);
        return;
    }
    i -= NW1;
    if (i < 3 * NW) {
        int w = (int)(i / NW);
        int r = (int)(i % NW);
        int n = r / 256, k = r % 256;
        if (w == 0) g_Wq2[r] = f2tf32f(w2[k * 256 + n]);
        else if (w == 1) g_Wq3[r] = f2tf32f(w3[k * 256 + n]);
        else g_Wq4[r] = f2tf32f(w4[k * 256 + n]);
        return;
    }
    i -= 3 * NW;
    if (i < (long long)NN * 128) g_X[i] = f2tf32f(x[i]);
}

// ---------------- CSR build --------------------------------------------------
__global__ void k_zero_cnt() {
    int i = blockIdx.x * blockDim.x + threadIdx.x;
    if (i < NN) g_cursor[i] = 0;
}

__global__ void k_hist(const int* __restrict__ row) {
    int e = blockIdx.x * blockDim.x + threadIdx.x;
    if (e < EE) atomicAdd(&g_cursor[row[e]], 1);
}

__global__ void k_scan1() {
    __shared__ int s[SCAN_BLK];
    int t = threadIdx.x;
    int gid = blockIdx.x * SCAN_BLK + t;
    s[t] = (gid < NN) ? g_cursor[gid] : 0;
    for (int d = 1; d < SCAN_BLK; d <<= 1) {
        __syncthreads();
        int u = (t >= d) ? s[t - d] : 0;
        __syncthreads();
        s[t] += u;
    }
    __syncthreads();
    if (gid < NN) g_rowptr[gid + 1] = s[t];
    if (t == SCAN_BLK - 1) g_blocksums[blockIdx.x] = s[t];
}

__global__ void k_scan23() {
    __shared__ int s[128];
    int t = threadIdx.x;
    if (t < 128) s[t] = (t < NSCANBLK) ? g_blocksums[t] : 0;
    __syncthreads();
    if (t < 128) {
        for (int d = 1; d < 128; d <<= 1) {
            __syncthreads();
            int u = (t >= d) ? s[t - d] : 0;
            __syncthreads();
            s[t] += u;
        }
    } else {
        for (int d = 1; d < 128; d <<= 1) { __syncthreads(); __syncthreads(); }
    }
    __syncthreads();
    for (int i = t; i < NN; i += SCAN_BLK) {
        int b = i >> 10;
        int off = b ? s[b - 1] : 0;
        g_rowptr[i + 1] += off;
    }
    if (t == 0) g_rowptr[0] = 0;
    __syncthreads();
    for (int i = t; i < NN; i += SCAN_BLK)
        g_cursor[i] = g_rowptr[i];
}

__global__ void k_scatter(const int* __restrict__ row, const int* __restrict__ col,
                          const float* __restrict__ val) {
    int e = blockIdx.x * blockDim.x + threadIdx.x;
    if (e < EE) {
        int r = row[e];
        int p = atomicAdd(&g_cursor[r], 1);
        g_col[p] = col[e];
        g_val[p] = val[e];
    }
}

// ---------------- tf32 mma.sync GEMM: C[M,256] = A[M,K] @ W[K,256] ----------
// Bw is W in [N=256][K] K-major layout (pre-rounded tf32 values).
// BM=128, BN=128, BK=32, 256 threads (8 warps: 2(M) x 4(N)), warp tile 64x32.
#define GBM 128
#define GBN 128
#define GBK 32
#define GPAD 36
#define TILE_WORDS (GBM * GPAD)          // 4608 words per A or B tile

__global__ void __launch_bounds__(256, 2) k_gemm_mma(
    const float* __restrict__ A, const float* __restrict__ Bw,
    float* __restrict__ C, int M, int K) {
    extern __shared__ float sm[];
    uint32_t sb = smem_u32(sm);
    int tid = threadIdx.x;
    int wid = tid >> 5, lane = tid & 31;
    int wm = wid & 1, wn = wid >> 1;
    int gid = lane >> 2, tg = lane & 3;

    int row0 = blockIdx.x * GBM;
    int col0 = blockIdx.y * GBN;
    int nIter = K >> 5;

    // smem word offsets: [A0 | B0 | A1 | B1]
    const int aoff[2] = {0, 2 * TILE_WORDS};
    const int boff[2] = {TILE_WORDS, 3 * TILE_WORDS};

    float acc[4][4][4];
#pragma unroll
    for (int i = 0; i < 4; i++)
#pragma unroll
        for (int j = 0; j < 4; j++)
#pragma unroll
            for (int k = 0; k < 4; k++) acc[i][j][k] = 0.f;

    // stage tile c into buffer buf
    auto stage = [&](int c, int buf) {
        int k0 = c * GBK;
        const float* Ag = A + (size_t)row0 * K + k0;
#pragma unroll
        for (int it = 0; it < 4; it++) {
            int idx = tid + it * 256;
            int r = idx >> 3, c4 = idx & 7;
            if (row0 + r < M)
                cpasync16(sb + (uint32_t)(aoff[buf] + r * GPAD + c4 * 4) * 4,
                          Ag + (size_t)r * K + c4 * 4);
        }
        const float* Bg = Bw + (size_t)col0 * K + k0;
#pragma unroll
        for (int it = 0; it < 4; it++) {
            int idx = tid + it * 256;
            int r = idx >> 3, c4 = idx & 7;
            cpasync16(sb + (uint32_t)(boff[buf] + r * GPAD + c4 * 4) * 4,
                      Bg + (size_t)r * K + c4 * 4);
        }
        asm volatile("cp.async.commit_group;" ::: "memory");
    };

    stage(0, 0);

    for (int c = 0; c < nIter; c++) {
        int buf = c & 1;
        if (c + 1 < nIter) {
            stage(c + 1, buf ^ 1);
            asm volatile("cp.async.wait_group 1;" ::: "memory");
        } else {
            asm volatile("cp.async.wait_group 0;" ::: "memory");
        }
        __syncthreads();

        const uint32_t* As = (const uint32_t*)(sm + aoff[buf]);
        const uint32_t* Bs = (const uint32_t*)(sm + boff[buf]);

#pragma unroll
        for (int ks = 0; ks < 4; ks++) {
            int k = ks * 8;
            uint32_t a[4][4], b[4][2];
#pragma unroll
            for (int mt = 0; mt < 4; mt++) {
                int rb = wm * 64 + mt * 16 + gid;
                a[mt][0] = As[rb * GPAD + k + tg];
                a[mt][1] = As[(rb + 8) * GPAD + k + tg];
                a[mt][2] = As[rb * GPAD + k + tg + 4];
                a[mt][3] = As[(rb + 8) * GPAD + k + tg + 4];
            }
#pragma unroll
            for (int nt = 0; nt < 4; nt++) {
                int nb = wn * 32 + nt * 8 + gid;
                b[nt][0] = Bs[nb * GPAD + k + tg];
                b[nt][1] = Bs[nb * GPAD + k + tg + 4];
            }
#pragma unroll
            for (int mt = 0; mt < 4; mt++)
#pragma unroll
                for (int nt = 0; nt < 4; nt++) {
                    float* d = acc[mt][nt];
                    asm volatile(
                        "mma.sync.aligned.m16n8k8.row.col.f32.tf32.tf32.f32 "
                        "{%0,%1,%2,%3}, {%4,%5,%6,%7}, {%8,%9}, {%0,%1,%2,%3};"
                        : "+f"(d[0]), "+f"(d[1]), "+f"(d[2]), "+f"(d[3])
                        : "r"(a[mt][0]), "r"(a[mt][1]), "r"(a[mt][2]), "r"(a[mt][3]),
                          "r"(b[nt][0]), "r"(b[nt][1]));
                }
        }
        __syncthreads();
    }

    // epilogue
#pragma unroll
    for (int mt = 0; mt < 4; mt++) {
        int rg = row0 + wm * 64 + mt * 16 + gid;
#pragma unroll
        for (int nt = 0; nt < 4; nt++) {
            int cg = col0 + wn * 32 + nt * 8 + tg * 2;
            if (rg < M)
                *(float2*)(C + (size_t)rg * 256 + cg) =
                    make_float2(acc[mt][nt][0], acc[mt][nt][1]);
            if (rg + 8 < M)
                *(float2*)(C + (size_t)(rg + 8) * 256 + cg) =
                    make_float2(acc[mt][nt][2], acc[mt][nt][3]);
        }
    }
}

// ---------------- SpMM (CSR) + bias + relu (+ tf32 rounding of output) ------
__global__ void k_spmm_bias_relu(const float* __restrict__ S,
                                 const float* __restrict__ bias,
                                 float* __restrict__ out, int roundOut) {
    int w = (blockIdx.x * blockDim.x + threadIdx.x) >> 5;
    if (w >= NN) return;
    int lane = threadIdx.x & 31;
    const float4* S4 = (const float4*)S;

    float4 a0 = make_float4(0.f, 0.f, 0.f, 0.f);
    float4 a1 = make_float4(0.f, 0.f, 0.f, 0.f);

    int s = g_rowptr[w], e = g_rowptr[w + 1];
    for (int base = s; base < e; base += 32) {
        int idx = base + lane;
        int c = 0;
        float v = 0.f;
        if (idx < e) { c = g_col[idx]; v = g_val[idx]; }
        int m = min(32, e - base);
        if (m == 32) {
#pragma unroll 8
            for (int j = 0; j < 32; j++) {
                int cj = __shfl_sync(0xffffffffu, c, j);
                float vj = __shfl_sync(0xffffffffu, v, j);
                float4 p0 = S4[(size_t)cj * 64 + lane];
                float4 p1 = S4[(size_t)cj * 64 + 32 + lane];
                a0.x += vj * p0.x; a0.y += vj * p0.y; a0.z += vj * p0.z; a0.w += vj * p0.w;
                a1.x += vj * p1.x; a1.y += vj * p1.y; a1.z += vj * p1.z; a1.w += vj * p1.w;
            }
        } else {
            for (int j = 0; j < m; j++) {
                int cj = __shfl_sync(0xffffffffu, c, j);
                float vj = __shfl_sync(0xffffffffu, v, j);
                float4 p0 = S4[(size_t)cj * 64 + lane];
                float4 p1 = S4[(size_t)cj * 64 + 32 + lane];
                a0.x += vj * p0.x; a0.y += vj * p0.y; a0.z += vj * p0.z; a0.w += vj * p0.w;
                a1.x += vj * p1.x; a1.y += vj * p1.y; a1.z += vj * p1.z; a1.w += vj * p1.w;
            }
        }
    }
    float4 b0 = ((const float4*)bias)[lane];
    float4 b1 = ((const float4*)bias)[32 + lane];
    a0.x = fmaxf(a0.x + b0.x, 0.f); a0.y = fmaxf(a0.y + b0.y, 0.f);
    a0.z = fmaxf(a0.z + b0.z, 0.f); a0.w = fmaxf(a0.w + b0.w, 0.f);
    a1.x = fmaxf(a1.x + b1.x, 0.f); a1.y = fmaxf(a1.y + b1.y, 0.f);
    a1.z = fmaxf(a1.z + b1.z, 0.f); a1.w = fmaxf(a1.w + b1.w, 0.f);
    if (roundOut) {
        a0.x = f2tf32f(a0.x); a0.y = f2tf32f(a0.y); a0.z = f2tf32f(a0.z); a0.w = f2tf32f(a0.w);
        a1.x = f2tf32f(a1.x); a1.y = f2tf32f(a1.y); a1.z = f2tf32f(a1.z); a1.w = f2tf32f(a1.w);
    }
    ((float4*)out)[(size_t)w * 64 + lane] = a0;
    ((float4*)out)[(size_t)w * 64 + 32 + lane] = a1;
}

// ---------------- fused FC + log_softmax ------------------------------------
__global__ void k_fc_lsm(const float* __restrict__ H, const float* __restrict__ fw,
                         const float* __restrict__ fb, float* __restrict__ out) {
    __shared__ float sh[8][NHID];
    int wIn = threadIdx.x >> 5;
    int lane = threadIdx.x & 31;
    int i = blockIdx.x * 8 + wIn;
    if (i >= NN) return;
#pragma unroll
    for (int j = 0; j < 8; j++)
        sh[wIn][j * 32 + lane] = H[(size_t)i * NHID + j * 32 + lane];
    __syncwarp();
    if (lane < NCLASS) {
        float acc = fb[lane];
#pragma unroll 8
        for (int k = 0; k < NHID; k++) acc += sh[wIn][k] * fw[k * NCLASS + lane];
        float mx = acc;
#pragma unroll
        for (int o = 8; o; o >>= 1) mx = fmaxf(mx, __shfl_xor_sync(0xffffu, mx, o));
        float ex = expf(acc - mx);
        float sm = ex;
#pragma unroll
        for (int o = 8; o; o >>= 1) sm += __shfl_xor_sync(0xffffu, sm, o);
        out[(size_t)i * NCLASS + lane] = (acc - mx) - logf(sm);
    }
}

// ---------------- launch -----------------------------------------------------
extern "C" void kernel_launch(void* const* d_in, const int* in_sizes, int n_in,
                              void* d_out, int out_size) {
    const float* x    = (const float*)d_in[0];
    const float* adj_val = (const float*)d_in[1];
    const float* w1 = (const float*)d_in[2];
    const float* b1 = (const float*)d_in[3];
    const float* w2 = (const float*)d_in[4];
    const float* b2 = (const float*)d_in[5];
    const float* w3 = (const float*)d_in[6];
    const float* b3 = (const float*)d_in[7];
    const float* w4 = (const float*)d_in[8];
    const float* b4 = (const float*)d_in[9];
    const float* fc_w = (const float*)d_in[10];
    const float* fc_b = (const float*)d_in[11];
    const int* adj_row = (const int*)d_in[12];
    const int* adj_col = (const int*)d_in[13];
    float* out = (float*)d_out;

    float* S;  cudaGetSymbolAddress((void**)&S, g_S);
    float* Ab; cudaGetSymbolAddress((void**)&Ab, g_A);
    float* Bb; cudaGetSymbolAddress((void**)&Bb, g_B);
    float* Xq; cudaGetSymbolAddress((void**)&Xq, g_X);
    float* Wq1; cudaGetSymbolAddress((void**)&Wq1, g_Wq1);
    float* Wq2; cudaGetSymbolAddress((void**)&Wq2, g_Wq2);
    float* Wq3; cudaGetSymbolAddress((void**)&Wq3, g_Wq3);
    float* Wq4; cudaGetSymbolAddress((void**)&Wq4, g_Wq4);

    const int GSMEM = 4 * TILE_WORDS * 4;   // 73728 bytes
    cudaFuncSetAttribute(k_gemm_mma, cudaFuncAttributeMaxDynamicSharedMemorySize, GSMEM);

    const int nThreads = 256;
    int nBlkN = (NN + nThreads - 1) / nThreads;
    int nBlkE = (EE + nThreads - 1) / nThreads;
    long long prepTotal = 256LL * 128 + 3LL * 256 * 256 + (long long)NN * 128;
    int prepBlk = (int)((prepTotal + nThreads - 1) / nThreads);

    dim3 gemmGrid((NN + GBM - 1) / GBM, 256 / GBN);
    int spmmBlocks = (NN * 32 + nThreads - 1) / nThreads;

    k_prep<<<prepBlk, nThreads>>>(x, w1, w2, w3, w4);           // 0
    k_zero_cnt<<<nBlkN, nThreads>>>();                           // 1
    k_hist<<<nBlkE, nThreads>>>(adj_row);                        // 2
    k_scan1<<<NSCANBLK, SCAN_BLK>>>();                           // 3
    k_scan23<<<1, SCAN_BLK>>>();                                 // 4
    k_gemm_mma<<<gemmGrid, nThreads, GSMEM>>>(Xq, Wq1, S, NN, 128);   // 5 (ncu)
    k_scatter<<<nBlkE, nThreads>>>(adj_row, adj_col, adj_val);   // 6
    k_spmm_bias_relu<<<spmmBlocks, nThreads>>>(S, b1, Ab, 1);    // 7

    k_gemm_mma<<<gemmGrid, nThreads, GSMEM>>>(Ab, Wq2, S, NN, 256);
    k_spmm_bias_relu<<<spmmBlocks, nThreads>>>(S, b2, Bb, 1);
    k_gemm_mma<<<gemmGrid, nThreads, GSMEM>>>(Bb, Wq3, S, NN, 256);
    k_spmm_bias_relu<<<spmmBlocks, nThreads>>>(S, b3, Ab, 1);
    k_gemm_mma<<<gemmGrid, nThreads, GSMEM>>>(Ab, Wq4, S, NN, 256);
    k_spmm_bias_relu<<<spmmBlocks, nThreads>>>(S, b4, Bb, 0);

    int fcBlocks = (NN + 7) / 8;
    k_fc_lsm<<<fcBlocks, nThreads>>>(Bb, fc_w, fc_b, out);
}

// round 4
// speedup vs baseline: 1.9115x; 1.2498x over previous
#include <cuda_runtime.h>
#include <cuda_bf16.h>
#include <cuda_fp16.h>
#include <math.h>
#include <stdint.h>

#define NN 100000
#define EE 3200000
#define NHID 256
#define NCLASS 16
#define SCAN_BLK 1024
#define NSCANBLK ((NN + SCAN_BLK - 1) / SCAN_BLK)   // 98

// ---------------- scratch (static device globals) ---------------------------
__device__ __half g_Sh[(size_t)NN * NHID]; // GEMM output (fp16) / spmm input
__device__ float g_A[(size_t)NN * NHID];   // ping (spmm out)
__device__ float g_B[(size_t)NN * NHID];   // pong
__device__ float g_X[(size_t)NN * 128];    // tf32-rounded input x
__device__ int   g_col[EE];
__device__ float g_val[EE];
__device__ int   g_rowptr[NN + 1];
__device__ int   g_cursor[NN];
__device__ int   g_blocksums[SCAN_BLK];
__device__ float g_Wq1[256 * 128];         // weights: [n][k] K-major, tf32-rounded
__device__ float g_Wq2[256 * 256];
__device__ float g_Wq3[256 * 256];
__device__ float g_Wq4[256 * 256];

__device__ __forceinline__ float f2tf32f(float x) {
    uint32_t r;
    asm("cvt.rna.tf32.f32 %0, %1;" : "=r"(r) : "f"(x));
    return __uint_as_float(r);
}

__device__ __forceinline__ uint32_t smem_u32(const void* p) {
    uint32_t a;
    asm("{ .reg .u64 t; cvta.to.shared.u64 t, %1; cvt.u32.u64 %0, t; }"
        : "=r"(a) : "l"(p));
    return a;
}

__device__ __forceinline__ void cpasync16(uint32_t dst, const void* src) {
    asm volatile("cp.async.ca.shared.global [%0], [%1], 16;" :: "r"(dst), "l"(src));
}

// ---------------- prep: round x to tf32; transpose+round weights ------------
__global__ void k_prep(const float* __restrict__ x,
                       const float* __restrict__ w1, const float* __restrict__ w2,
                       const float* __restrict__ w3, const float* __restrict__ w4) {
    long long i = (long long)blockIdx.x * blockDim.x + threadIdx.x;
    const long long NW1 = 256 * 128;
    const long long NW = 256 * 256;
    if (i < NW1) {
        int n = (int)(i / 128), k = (int)(i % 128);
        g_Wq1[i] = f2tf32f(w1[k * 256 + n]);
        return;
    }
    i -= NW1;
    if (i < 3 * NW) {
        int w = (int)(i / NW);
        int r = (int)(i % NW);
        int n = r / 256, k = r % 256;
        if (w == 0) g_Wq2[r] = f2tf32f(w2[k * 256 + n]);
        else if (w == 1) g_Wq3[r] = f2tf32f(w3[k * 256 + n]);
        else g_Wq4[r] = f2tf32f(w4[k * 256 + n]);
        return;
    }
    i -= 3 * NW;
    if (i < (long long)NN * 128) g_X[i] = f2tf32f(x[i]);
}

// ---------------- CSR build --------------------------------------------------
__global__ void k_zero_cnt() {
    int i = blockIdx.x * blockDim.x + threadIdx.x;
    if (i < NN) g_cursor[i] = 0;
}

__global__ void k_hist(const int* __restrict__ row) {
    int e = blockIdx.x * blockDim.x + threadIdx.x;
    if (e < EE) atomicAdd(&g_cursor[row[e]], 1);
}

__global__ void k_scan1() {
    __shared__ int s[SCAN_BLK];
    int t = threadIdx.x;
    int gid = blockIdx.x * SCAN_BLK + t;
    s[t] = (gid < NN) ? g_cursor[gid] : 0;
    for (int d = 1; d < SCAN_BLK; d <<= 1) {
        __syncthreads();
        int u = (t >= d) ? s[t - d] : 0;
        __syncthreads();
        s[t] += u;
    }
    __syncthreads();
    if (gid < NN) g_rowptr[gid + 1] = s[t];
    if (t == SCAN_BLK - 1) g_blocksums[blockIdx.x] = s[t];
}

__global__ void k_scan23() {
    __shared__ int s[128];
    int t = threadIdx.x;
    if (t < 128) s[t] = (t < NSCANBLK) ? g_blocksums[t] : 0;
    __syncthreads();
    if (t < 128) {
        for (int d = 1; d < 128; d <<= 1) {
            __syncthreads();
            int u = (t >= d) ? s[t - d] : 0;
            __syncthreads();
            s[t] += u;
        }
    } else {
        for (int d = 1; d < 128; d <<= 1) { __syncthreads(); __syncthreads(); }
    }
    __syncthreads();
    for (int i = t; i < NN; i += SCAN_BLK) {
        int b = i >> 10;
        int off = b ? s[b - 1] : 0;
        g_rowptr[i + 1] += off;
    }
    if (t == 0) g_rowptr[0] = 0;
    __syncthreads();
    for (int i = t; i < NN; i += SCAN_BLK)
        g_cursor[i] = g_rowptr[i];
}

__global__ void k_scatter(const int* __restrict__ row, const int* __restrict__ col,
                          const float* __restrict__ val) {
    int e = blockIdx.x * blockDim.x + threadIdx.x;
    if (e < EE) {
        int r = row[e];
        int p = atomicAdd(&g_cursor[r], 1);
        g_col[p] = col[e];
        g_val[p] = val[e];
    }
}

// ---------------- tf32 mma.sync GEMM: C[M,256] = A[M,K] @ W[K,256] ----------
// Bw is W in [N=256][K] K-major layout (pre-rounded tf32 values).
// BM=128, BN=128, BK=32, 256 threads (8 warps: 2(M) x 4(N)), warp tile 64x32.
// Output written as fp16.
#define GBM 128
#define GBN 128
#define GBK 32
#define GPAD 36
#define TILE_WORDS (GBM * GPAD)          // 4608 words per A or B tile

__global__ void __launch_bounds__(256, 2) k_gemm_mma(
    const float* __restrict__ A, const float* __restrict__ Bw,
    __half* __restrict__ C, int M, int K) {
    extern __shared__ float sm[];
    uint32_t sb = smem_u32(sm);
    int tid = threadIdx.x;
    int wid = tid >> 5, lane = tid & 31;
    int wm = wid & 1, wn = wid >> 1;
    int gid = lane >> 2, tg = lane & 3;

    int row0 = blockIdx.x * GBM;
    int col0 = blockIdx.y * GBN;
    int nIter = K >> 5;

    const int aoff[2] = {0, 2 * TILE_WORDS};
    const int boff[2] = {TILE_WORDS, 3 * TILE_WORDS};

    float acc[4][4][4];
#pragma unroll
    for (int i = 0; i < 4; i++)
#pragma unroll
        for (int j = 0; j < 4; j++)
#pragma unroll
            for (int k = 0; k < 4; k++) acc[i][j][k] = 0.f;

    auto stage = [&](int c, int buf) {
        int k0 = c * GBK;
        const float* Ag = A + (size_t)row0 * K + k0;
#pragma unroll
        for (int it = 0; it < 4; it++) {
            int idx = tid + it * 256;
            int r = idx >> 3, c4 = idx & 7;
            if (row0 + r < M)
                cpasync16(sb + (uint32_t)(aoff[buf] + r * GPAD + c4 * 4) * 4,
                          Ag + (size_t)r * K + c4 * 4);
        }
        const float* Bg = Bw + (size_t)col0 * K + k0;
#pragma unroll
        for (int it = 0; it < 4; it++) {
            int idx = tid + it * 256;
            int r = idx >> 3, c4 = idx & 7;
            cpasync16(sb + (uint32_t)(boff[buf] + r * GPAD + c4 * 4) * 4,
                      Bg + (size_t)r * K + c4 * 4);
        }
        asm volatile("cp.async.commit_group;" ::: "memory");
    };

    stage(0, 0);

    for (int c = 0; c < nIter; c++) {
        int buf = c & 1;
        if (c + 1 < nIter) {
            stage(c + 1, buf ^ 1);
            asm volatile("cp.async.wait_group 1;" ::: "memory");
        } else {
            asm volatile("cp.async.wait_group 0;" ::: "memory");
        }
        __syncthreads();

        const uint32_t* As = (const uint32_t*)(sm + aoff[buf]);
        const uint32_t* Bs = (const uint32_t*)(sm + boff[buf]);

#pragma unroll
        for (int ks = 0; ks < 4; ks++) {
            int k = ks * 8;
            uint32_t a[4][4], b[4][2];
#pragma unroll
            for (int mt = 0; mt < 4; mt++) {
                int rb = wm * 64 + mt * 16 + gid;
                a[mt][0] = As[rb * GPAD + k + tg];
                a[mt][1] = As[(rb + 8) * GPAD + k + tg];
                a[mt][2] = As[rb * GPAD + k + tg + 4];
                a[mt][3] = As[(rb + 8) * GPAD + k + tg + 4];
            }
#pragma unroll
            for (int nt = 0; nt < 4; nt++) {
                int nb = wn * 32 + nt * 8 + gid;
                b[nt][0] = Bs[nb * GPAD + k + tg];
                b[nt][1] = Bs[nb * GPAD + k + tg + 4];
            }
#pragma unroll
            for (int mt = 0; mt < 4; mt++)
#pragma unroll
                for (int nt = 0; nt < 4; nt++) {
                    float* d = acc[mt][nt];
                    asm volatile(
                        "mma.sync.aligned.m16n8k8.row.col.f32.tf32.tf32.f32 "
                        "{%0,%1,%2,%3}, {%4,%5,%6,%7}, {%8,%9}, {%0,%1,%2,%3};"
                        : "+f"(d[0]), "+f"(d[1]), "+f"(d[2]), "+f"(d[3])
                        : "r"(a[mt][0]), "r"(a[mt][1]), "r"(a[mt][2]), "r"(a[mt][3]),
                          "r"(b[nt][0]), "r"(b[nt][1]));
                }
        }
        __syncthreads();
    }

    // epilogue: convert fp32 acc -> fp16, store half2
#pragma unroll
    for (int mt = 0; mt < 4; mt++) {
        int rg = row0 + wm * 64 + mt * 16 + gid;
#pragma unroll
        for (int nt = 0; nt < 4; nt++) {
            int cg = col0 + wn * 32 + nt * 8 + tg * 2;
            float* d = acc[mt][nt];
            if (rg < M)
                *(__half2*)(C + (size_t)rg * 256 + cg) = __floats2half2_rn(d[0], d[1]);
            if (rg + 8 < M)
                *(__half2*)(C + (size_t)(rg + 8) * 256 + cg) = __floats2half2_rn(d[2], d[3]);
        }
    }
}

// ---------------- SpMM (CSR, fp16 gather) + bias + relu ---------------------
// One warp per dest node. Row = 256 halves = 512B; lane owns 8 cols (16B uint4).
__global__ void k_spmm_bias_relu(const __half* __restrict__ S,
                                 const float* __restrict__ bias,
                                 float* __restrict__ out, int roundOut) {
    int w = (blockIdx.x * blockDim.x + threadIdx.x) >> 5;
    if (w >= NN) return;
    int lane = threadIdx.x & 31;
    const uint4* S4 = (const uint4*)S;   // row stride 32 uint4

    float acc[8] = {0.f, 0.f, 0.f, 0.f, 0.f, 0.f, 0.f, 0.f};

    int s = g_rowptr[w], e = g_rowptr[w + 1];
    for (int base = s; base < e; base += 32) {
        int idx = base + lane;
        int c = 0;
        float v = 0.f;
        if (idx < e) { c = g_col[idx]; v = g_val[idx]; }
        int m = min(32, e - base);
        if (m == 32) {
#pragma unroll 8
            for (int j = 0; j < 32; j++) {
                int cj = __shfl_sync(0xffffffffu, c, j);
                float vj = __shfl_sync(0xffffffffu, v, j);
                uint4 q = S4[(size_t)cj * 32 + lane];
                const __half2* h = (const __half2*)&q;
                float2 f0 = __half22float2(h[0]);
                float2 f1 = __half22float2(h[1]);
                float2 f2 = __half22float2(h[2]);
                float2 f3 = __half22float2(h[3]);
                acc[0] += vj * f0.x; acc[1] += vj * f0.y;
                acc[2] += vj * f1.x; acc[3] += vj * f1.y;
                acc[4] += vj * f2.x; acc[5] += vj * f2.y;
                acc[6] += vj * f3.x; acc[7] += vj * f3.y;
            }
        } else {
            for (int j = 0; j < m; j++) {
                int cj = __shfl_sync(0xffffffffu, c, j);
                float vj = __shfl_sync(0xffffffffu, v, j);
                uint4 q = S4[(size_t)cj * 32 + lane];
                const __half2* h = (const __half2*)&q;
                float2 f0 = __half22float2(h[0]);
                float2 f1 = __half22float2(h[1]);
                float2 f2 = __half22float2(h[2]);
                float2 f3 = __half22float2(h[3]);
                acc[0] += vj * f0.x; acc[1] += vj * f0.y;
                acc[2] += vj * f1.x; acc[3] += vj * f1.y;
                acc[4] += vj * f2.x; acc[5] += vj * f2.y;
                acc[6] += vj * f3.x; acc[7] += vj * f3.y;
            }
        }
    }
    // bias + relu (+ tf32 round for next GEMM's A operand)
    float4 b0 = ((const float4*)bias)[lane * 2];
    float4 b1 = ((const float4*)bias)[lane * 2 + 1];
    float r0 = fmaxf(acc[0] + b0.x, 0.f), r1 = fmaxf(acc[1] + b0.y, 0.f);
    float r2 = fmaxf(acc[2] + b0.z, 0.f), r3 = fmaxf(acc[3] + b0.w, 0.f);
    float r4 = fmaxf(acc[4] + b1.x, 0.f), r5 = fmaxf(acc[5] + b1.y, 0.f);
    float r6 = fmaxf(acc[6] + b1.z, 0.f), r7 = fmaxf(acc[7] + b1.w, 0.f);
    if (roundOut) {
        r0 = f2tf32f(r0); r1 = f2tf32f(r1); r2 = f2tf32f(r2); r3 = f2tf32f(r3);
        r4 = f2tf32f(r4); r5 = f2tf32f(r5); r6 = f2tf32f(r6); r7 = f2tf32f(r7);
    }
    float4* o = (float4*)(out + (size_t)w * 256 + lane * 8);
    o[0] = make_float4(r0, r1, r2, r3);
    o[1] = make_float4(r4, r5, r6, r7);
}

// ---------------- fused FC + log_softmax ------------------------------------
__global__ void k_fc_lsm(const float* __restrict__ H, const float* __restrict__ fw,
                         const float* __restrict__ fb, float* __restrict__ out) {
    __shared__ float sh[8][NHID];
    int wIn = threadIdx.x >> 5;
    int lane = threadIdx.x & 31;
    int i = blockIdx.x * 8 + wIn;
    if (i >= NN) return;
#pragma unroll
    for (int j = 0; j < 8; j++)
        sh[wIn][j * 32 + lane] = H[(size_t)i * NHID + j * 32 + lane];
    __syncwarp();
    if (lane < NCLASS) {
        float acc = fb[lane];
#pragma unroll 8
        for (int k = 0; k < NHID; k++) acc += sh[wIn][k] * fw[k * NCLASS + lane];
        float mx = acc;
#pragma unroll
        for (int o = 8; o; o >>= 1) mx = fmaxf(mx, __shfl_xor_sync(0xffffu, mx, o));
        float ex = expf(acc - mx);
        float sm = ex;
#pragma unroll
        for (int o = 8; o; o >>= 1) sm += __shfl_xor_sync(0xffffu, sm, o);
        out[(size_t)i * NCLASS + lane] = (acc - mx) - logf(sm);
    }
}

// ---------------- launch -----------------------------------------------------
extern "C" void kernel_launch(void* const* d_in, const int* in_sizes, int n_in,
                              void* d_out, int out_size) {
    const float* x    = (const float*)d_in[0];
    const float* adj_val = (const float*)d_in[1];
    const float* w1 = (const float*)d_in[2];
    const float* b1 = (const float*)d_in[3];
    const float* w2 = (const float*)d_in[4];
    const float* b2 = (const float*)d_in[5];
    const float* w3 = (const float*)d_in[6];
    const float* b3 = (const float*)d_in[7];
    const float* w4 = (const float*)d_in[8];
    const float* b4 = (const float*)d_in[9];
    const float* fc_w = (const float*)d_in[10];
    const float* fc_b = (const float*)d_in[11];
    const int* adj_row = (const int*)d_in[12];
    const int* adj_col = (const int*)d_in[13];
    float* out = (float*)d_out;

    __half* Sh; cudaGetSymbolAddress((void**)&Sh, g_Sh);
    float* Ab; cudaGetSymbolAddress((void**)&Ab, g_A);
    float* Bb; cudaGetSymbolAddress((void**)&Bb, g_B);
    float* Xq; cudaGetSymbolAddress((void**)&Xq, g_X);
    float* Wq1; cudaGetSymbolAddress((void**)&Wq1, g_Wq1);
    float* Wq2; cudaGetSymbolAddress((void**)&Wq2, g_Wq2);
    float* Wq3; cudaGetSymbolAddress((void**)&Wq3, g_Wq3);
    float* Wq4; cudaGetSymbolAddress((void**)&Wq4, g_Wq4);

    const int GSMEM = 4 * TILE_WORDS * 4;   // 73728 bytes
    cudaFuncSetAttribute(k_gemm_mma, cudaFuncAttributeMaxDynamicSharedMemorySize, GSMEM);

    const int nThreads = 256;
    int nBlkN = (NN + nThreads - 1) / nThreads;
    int nBlkE = (EE + nThreads - 1) / nThreads;
    long long prepTotal = 256LL * 128 + 3LL * 256 * 256 + (long long)NN * 128;
    int prepBlk = (int)((prepTotal + nThreads - 1) / nThreads);

    dim3 gemmGrid((NN + GBM - 1) / GBM, 256 / GBN);
    int spmmBlocks = (NN * 32 + nThreads - 1) / nThreads;

    k_prep<<<prepBlk, nThreads>>>(x, w1, w2, w3, w4);           // 0
    k_zero_cnt<<<nBlkN, nThreads>>>();                           // 1
    k_hist<<<nBlkE, nThreads>>>(adj_row);                        // 2
    k_scan1<<<NSCANBLK, SCAN_BLK>>>();                           // 3
    k_scan23<<<1, SCAN_BLK>>>();                                 // 4
    k_gemm_mma<<<gemmGrid, nThreads, GSMEM>>>(Xq, Wq1, Sh, NN, 128);  // 5
    k_scatter<<<nBlkE, nThreads>>>(adj_row, adj_col, adj_val);   // 6
    k_spmm_bias_relu<<<spmmBlocks, nThreads>>>(Sh, b1, Ab, 1);   // 7

    k_gemm_mma<<<gemmGrid, nThreads, GSMEM>>>(Ab, Wq2, Sh, NN, 256);
    k_spmm_bias_relu<<<spmmBlocks, nThreads>>>(Sh, b2, Bb, 1);
    k_gemm_mma<<<gemmGrid, nThreads, GSMEM>>>(Bb, Wq3, Sh, NN, 256);
    k_spmm_bias_relu<<<spmmBlocks, nThreads>>>(Sh, b3, Ab, 1);
    k_gemm_mma<<<gemmGrid, nThreads, GSMEM>>>(Ab, Wq4, Sh, NN, 256);
    k_spmm_bias_relu<<<spmmBlocks, nThreads>>>(Sh, b4, Bb, 0);

    int fcBlocks = (NN + 7) / 8;
    k_fc_lsm<<<fcBlocks, nThreads>>>(Bb, fc_w, fc_b, out);
}

// round 7
// speedup vs baseline: 2.4585x; 1.2862x over previous
#include <cuda_runtime.h>
#include <cuda_fp16.h>
#include <math.h>
#include <stdint.h>

#define NN 100000
#define EE 3200000
#define NHID 256
#define NCLASS 16
#define SCAN_BLK 1024
#define NSCANBLK ((NN + SCAN_BLK - 1) / SCAN_BLK)   // 98

// ---------------- scratch (static device globals) ---------------------------
__device__ __half g_Xh[(size_t)NN * 128];   // x in fp16
__device__ __half g_H[(size_t)NN * 256];    // GEMM output (layer act), fp16 (scaled)
__device__ __half g_Agg[(size_t)NN * 256];  // SpMM output, fp16 (scaled)
__device__ int    g_col[EE];
__device__ float  g_val[EE];
__device__ int    g_rowptr[NN + 1];
__device__ int    g_cursor[NN];
__device__ int    g_blocksums[SCAN_BLK];
__device__ __half g_Wh1[256 * 128];         // weights [n][k] K-major fp16
__device__ __half g_Wh2[256 * 256];
__device__ __half g_Wh3[256 * 256];
__device__ __half g_Wh4[256 * 256];

__device__ __forceinline__ uint32_t smem_u32(const void* p) {
    uint32_t a;
    asm("{ .reg .u64 t; cvta.to.shared.u64 t, %1; cvt.u32.u64 %0, t; }"
        : "=r"(a) : "l"(p));
    return a;
}

__device__ __forceinline__ void cpasync16(uint32_t dst, const void* src) {
    asm volatile("cp.async.ca.shared.global [%0], [%1], 16;" :: "r"(dst), "l"(src));
}

// ---------------- prep: fp16 conversions -------------------------------------
__global__ void k_prep(const float* __restrict__ x,
                       const float* __restrict__ w1, const float* __restrict__ w2,
                       const float* __restrict__ w3, const float* __restrict__ w4) {
    long long i = (long long)blockIdx.x * blockDim.x + threadIdx.x;
    const long long NW1 = 256 * 128;
    const long long NW = 256 * 256;
    if (i < NW1) {
        int n = (int)(i / 128), k = (int)(i % 128);
        g_Wh1[i] = __float2half_rn(w1[k * 256 + n]);
        return;
    }
    i -= NW1;
    if (i < 3 * NW) {
        int w = (int)(i / NW);
        int r = (int)(i % NW);
        int n = r / 256, k = r % 256;
        if (w == 0) g_Wh2[r] = __float2half_rn(w2[k * 256 + n]);
        else if (w == 1) g_Wh3[r] = __float2half_rn(w3[k * 256 + n]);
        else g_Wh4[r] = __float2half_rn(w4[k * 256 + n]);
        return;
    }
    i -= 3 * NW;
    if (i < (long long)NN * 128) g_Xh[i] = __float2half_rn(x[i]);
}

// ---------------- CSR build --------------------------------------------------
__global__ void k_zero_cnt() {
    int i = blockIdx.x * blockDim.x + threadIdx.x;
    if (i < NN) g_cursor[i] = 0;
}

__global__ void k_hist(const int* __restrict__ row) {
    int e = blockIdx.x * blockDim.x + threadIdx.x;
    if (e < EE) atomicAdd(&g_cursor[row[e]], 1);
}

__global__ void k_scan1() {
    __shared__ int s[SCAN_BLK];
    int t = threadIdx.x;
    int gid = blockIdx.x * SCAN_BLK + t;
    s[t] = (gid < NN) ? g_cursor[gid] : 0;
    for (int d = 1; d < SCAN_BLK; d <<= 1) {
        __syncthreads();
        int u = (t >= d) ? s[t - d] : 0;
        __syncthreads();
        s[t] += u;
    }
    __syncthreads();
    if (gid < NN) g_rowptr[gid + 1] = s[t];
    if (t == SCAN_BLK - 1) g_blocksums[blockIdx.x] = s[t];
}

__global__ void k_scan23() {
    __shared__ int s[128];
    int t = threadIdx.x;
    if (t < 128) s[t] = (t < NSCANBLK) ? g_blocksums[t] : 0;
    __syncthreads();
    if (t < 128) {
        for (int d = 1; d < 128; d <<= 1) {
            __syncthreads();
            int u = (t >= d) ? s[t - d] : 0;
            __syncthreads();
            s[t] += u;
        }
    } else {
        for (int d = 1; d < 128; d <<= 1) { __syncthreads(); __syncthreads(); }
    }
    __syncthreads();
    for (int i = t; i < NN; i += SCAN_BLK) {
        int b = i >> 10;
        int off = b ? s[b - 1] : 0;
        g_rowptr[i + 1] += off;
    }
    if (t == 0) g_rowptr[0] = 0;
    __syncthreads();
    for (int i = t; i < NN; i += SCAN_BLK)
        g_cursor[i] = g_rowptr[i];
}

__global__ void k_scatter(const int* __restrict__ row, const int* __restrict__ col,
                          const float* __restrict__ val) {
    int e = blockIdx.x * blockDim.x + threadIdx.x;
    if (e < EE) {
        int r = row[e];
        int p = atomicAdd(&g_cursor[r], 1);
        g_col[p] = col[e];
        g_val[p] = val[e];
    }
}

// ---------------- SpMM (CSR, fp16 gather -> fp16 out, scaled by 1/4) --------
// One warp per dest node. NC = 128 (layer 1) or 256.
template <int NC>
__global__ void k_spmm(const __half* __restrict__ S, __half* __restrict__ out) {
    int w = (blockIdx.x * blockDim.x + threadIdx.x) >> 5;
    if (w >= NN) return;
    int lane = threadIdx.x & 31;
    constexpr int HP = NC / 32;          // halves per lane: 4 or 8

    float acc[HP];
#pragma unroll
    for (int i = 0; i < HP; i++) acc[i] = 0.f;

    int s = g_rowptr[w], e = g_rowptr[w + 1];
    for (int base = s; base < e; base += 32) {
        int idx = base + lane;
        int c = 0;
        float v = 0.f;
        if (idx < e) { c = g_col[idx]; v = g_val[idx]; }
        int m = min(32, e - base);
#pragma unroll 8
        for (int j = 0; j < 32; j++) {
            if (j >= m) break;
            int cj = __shfl_sync(0xffffffffu, c, j);
            float vj = __shfl_sync(0xffffffffu, v, j);
            if (NC == 256) {
                // 256 halves/row = 32 uint4 per row
                uint4 q = ((const uint4*)S)[(size_t)cj * 32 + lane];
                const __half2* h = (const __half2*)&q;
#pragma unroll
                for (int p = 0; p < 4; p++) {
                    float2 f = __half22float2(h[p]);
                    acc[p * 2] += vj * f.x;
                    acc[p * 2 + 1] += vj * f.y;
                }
            } else {
                // 128 halves/row = 32 uint2 per row
                uint2 q = ((const uint2*)S)[(size_t)cj * 32 + lane];
                const __half2* h = (const __half2*)&q;
#pragma unroll
                for (int p = 0; p < 2; p++) {
                    float2 f = __half22float2(h[p]);
                    acc[p * 2] += vj * f.x;
                    acc[p * 2 + 1] += vj * f.y;
                }
            }
        }
    }
    // write fp16, scaled by 1/4 (exact power-of-2) for fp16 range safety
    const float SC = 0.25f;
    __half2 o[HP / 2];
#pragma unroll
    for (int p = 0; p < HP / 2; p++)
        o[p] = __floats2half2_rn(acc[p * 2] * SC, acc[p * 2 + 1] * SC);
    if (NC == 256)
        ((uint4*)out)[(size_t)w * 32 + lane] = *(uint4*)o;
    else
        ((uint2*)out)[(size_t)w * 32 + lane] = *(uint2*)o;
}

// ---------------- fp16 HMMA GEMM + fused (scaled) bias + relu ----------------
// stored_C = relu( stored_A @ W + bias*bscale ), all at running scale 1/sigma.
#define HBK 64
#define HROW 72                        // +8 halves pad (16B)
#define HTILE_HALVES (128 * HROW)      // 9216 halves = 18432 B per tile

__global__ void __launch_bounds__(256, 2) k_gemm_h(
    const __half* __restrict__ A, const __half* __restrict__ Wt,
    const float* __restrict__ bias, float bscale,
    __half* __restrict__ C, int M, int K) {
    extern __shared__ __half sm[];
    uint32_t sb = smem_u32(sm);
    int tid = threadIdx.x;
    int wid = tid >> 5, lane = tid & 31;
    int wm = wid & 1, wn = wid >> 1;
    int gid = lane >> 2, tg = lane & 3;

    int row0 = blockIdx.x * 128;
    int col0 = blockIdx.y * 128;
    int nIter = K / HBK;

    const int aoff[2] = {0, 2 * HTILE_HALVES};
    const int boff[2] = {HTILE_HALVES, 3 * HTILE_HALVES};

    float acc[4][4][4];
#pragma unroll
    for (int i = 0; i < 4; i++)
#pragma unroll
        for (int j = 0; j < 4; j++)
#pragma unroll
            for (int k = 0; k < 4; k++) acc[i][j][k] = 0.f;

    auto stage = [&](int c, int buf) {
        int k0 = c * HBK;
        const __half* Ag = A + (size_t)row0 * K + k0;
#pragma unroll
        for (int it = 0; it < 4; it++) {
            int idx = tid + it * 256;            // 0..1023
            int r = idx >> 3, c8 = idx & 7;      // r:0..127, c8:0..7 (16B chunks)
            if (row0 + r < M)
                cpasync16(sb + (uint32_t)(aoff[buf] + r * HROW) * 2 + c8 * 16,
                          Ag + (size_t)r * K + c8 * 8);
        }
        const __half* Bg = Wt + (size_t)col0 * K + k0;
#pragma unroll
        for (int it = 0; it < 4; it++) {
            int idx = tid + it * 256;
            int r = idx >> 3, c8 = idx & 7;
            cpasync16(sb + (uint32_t)(boff[buf] + r * HROW) * 2 + c8 * 16,
                      Bg + (size_t)r * K + c8 * 8);
        }
        asm volatile("cp.async.commit_group;" ::: "memory");
    };

    stage(0, 0);

    for (int c = 0; c < nIter; c++) {
        int buf = c & 1;
        if (c + 1 < nIter) {
            stage(c + 1, buf ^ 1);
            asm volatile("cp.async.wait_group 1;" ::: "memory");
        } else {
            asm volatile("cp.async.wait_group 0;" ::: "memory");
        }
        __syncthreads();

        const uint32_t* As = (const uint32_t*)(sm + aoff[buf]);
        const uint32_t* Bs = (const uint32_t*)(sm + boff[buf]);

#pragma unroll
        for (int ks = 0; ks < 4; ks++) {
            int k = ks * 16;                     // halves; u32 index = /2
            uint32_t a[4][4], b[4][2];
#pragma unroll
            for (int mt = 0; mt < 4; mt++) {
                int rb = wm * 64 + mt * 16 + gid;
                int base0 = (rb * HROW + k) >> 1;        // u32 index
                int base1 = ((rb + 8) * HROW + k) >> 1;
                a[mt][0] = As[base0 + tg];
                a[mt][1] = As[base1 + tg];
                a[mt][2] = As[base0 + tg + 4];
                a[mt][3] = As[base1 + tg + 4];
            }
#pragma unroll
            for (int nt = 0; nt < 4; nt++) {
                int nb = wn * 32 + nt * 8 + gid;
                int base = (nb * HROW + k) >> 1;
                b[nt][0] = Bs[base + tg];
                b[nt][1] = Bs[base + tg + 4];
            }
#pragma unroll
            for (int mt = 0; mt < 4; mt++)
#pragma unroll
                for (int nt = 0; nt < 4; nt++) {
                    float* d = acc[mt][nt];
                    asm volatile(
                        "mma.sync.aligned.m16n8k16.row.col.f32.f16.f16.f32 "
                        "{%0,%1,%2,%3}, {%4,%5,%6,%7}, {%8,%9}, {%0,%1,%2,%3};"
                        : "+f"(d[0]), "+f"(d[1]), "+f"(d[2]), "+f"(d[3])
                        : "r"(a[mt][0]), "r"(a[mt][1]), "r"(a[mt][2]), "r"(a[mt][3]),
                          "r"(b[nt][0]), "r"(b[nt][1]));
                }
        }
        __syncthreads();
    }

    // epilogue: scaled bias + relu -> fp16
#pragma unroll
    for (int nt = 0; nt < 4; nt++) {
        int cg = col0 + wn * 32 + nt * 8 + tg * 2;
        float bx = bias[cg] * bscale, by = bias[cg + 1] * bscale;
#pragma unroll
        for (int mt = 0; mt < 4; mt++) {
            int rg = row0 + wm * 64 + mt * 16 + gid;
            float* d = acc[mt][nt];
            if (rg < M) {
                float v0 = fmaxf(d[0] + bx, 0.f);
                float v1 = fmaxf(d[1] + by, 0.f);
                *(__half2*)(C + (size_t)rg * 256 + cg) = __floats2half2_rn(v0, v1);
            }
            if (rg + 8 < M) {
                float v2 = fmaxf(d[2] + bx, 0.f);
                float v3 = fmaxf(d[3] + by, 0.f);
                *(__half2*)(C + (size_t)(rg + 8) * 256 + cg) = __floats2half2_rn(v2, v3);
            }
        }
    }
}

// ---------------- fused FC + log_softmax (fp16 input at scale 1/256) ---------
__global__ void k_fc_lsm(const __half* __restrict__ H, const float* __restrict__ fw,
                         const float* __restrict__ fb, float* __restrict__ out) {
    __shared__ float sh[8][NHID];
    int wIn = threadIdx.x >> 5;
    int lane = threadIdx.x & 31;
    int i = blockIdx.x * 8 + wIn;
    if (i >= NN) return;
#pragma unroll
    for (int j = 0; j < 4; j++) {
        __half2 h = *(const __half2*)(H + (size_t)i * 256 + j * 64 + lane * 2);
        float2 f = __half22float2(h);
        sh[wIn][j * 64 + lane * 2] = f.x;
        sh[wIn][j * 64 + lane * 2 + 1] = f.y;
    }
    __syncwarp();
    if (lane < NCLASS) {
        float acc = 0.f;
#pragma unroll 8
        for (int k = 0; k < NHID; k++) acc += sh[wIn][k] * fw[k * NCLASS + lane];
        acc = acc * 256.f + fb[lane];   // undo running scale sigma4 = 4^4
        float mx = acc;
#pragma unroll
        for (int o = 8; o; o >>= 1) mx = fmaxf(mx, __shfl_xor_sync(0xffffu, mx, o));
        float ex = expf(acc - mx);
        float sm = ex;
#pragma unroll
        for (int o = 8; o; o >>= 1) sm += __shfl_xor_sync(0xffffu, sm, o);
        out[(size_t)i * NCLASS + lane] = (acc - mx) - logf(sm);
    }
}

// ---------------- launch -----------------------------------------------------
extern "C" void kernel_launch(void* const* d_in, const int* in_sizes, int n_in,
                              void* d_out, int out_size) {
    const float* x    = (const float*)d_in[0];
    const float* adj_val = (const float*)d_in[1];
    const float* w1 = (const float*)d_in[2];
    const float* b1 = (const float*)d_in[3];
    const float* w2 = (const float*)d_in[4];
    const float* b2 = (const float*)d_in[5];
    const float* w3 = (const float*)d_in[6];
    const float* b3 = (const float*)d_in[7];
    const float* w4 = (const float*)d_in[8];
    const float* b4 = (const float*)d_in[9];
    const float* fc_w = (const float*)d_in[10];
    const float* fc_b = (const float*)d_in[11];
    const int* adj_row = (const int*)d_in[12];
    const int* adj_col = (const int*)d_in[13];
    float* out = (float*)d_out;

    __half* Xh;  cudaGetSymbolAddress((void**)&Xh, g_Xh);
    __half* H;   cudaGetSymbolAddress((void**)&H, g_H);
    __half* Agg; cudaGetSymbolAddress((void**)&Agg, g_Agg);
    __half* Wh1; cudaGetSymbolAddress((void**)&Wh1, g_Wh1);
    __half* Wh2; cudaGetSymbolAddress((void**)&Wh2, g_Wh2);
    __half* Wh3; cudaGetSymbolAddress((void**)&Wh3, g_Wh3);
    __half* Wh4; cudaGetSymbolAddress((void**)&Wh4, g_Wh4);

    const int GSMEM = 4 * HTILE_HALVES * 2;   // 73728 bytes
    cudaFuncSetAttribute(k_gemm_h, cudaFuncAttributeMaxDynamicSharedMemorySize, GSMEM);

    const int nThreads = 256;
    int nBlkN = (NN + nThreads - 1) / nThreads;
    int nBlkE = (EE + nThreads - 1) / nThreads;
    long long prepTotal = 256LL * 128 + 3LL * 256 * 256 + (long long)NN * 128;
    int prepBlk = (int)((prepTotal + nThreads - 1) / nThreads);

    dim3 gemmGrid((NN + 127) / 128, 2);
    int spmmBlocks = (NN * 32 + nThreads - 1) / nThreads;

    k_prep<<<prepBlk, nThreads>>>(x, w1, w2, w3, w4);
    k_zero_cnt<<<nBlkN, nThreads>>>();
    k_hist<<<nBlkE, nThreads>>>(adj_row);
    k_scan1<<<NSCANBLK, SCAN_BLK>>>();
    k_scan23<<<1, SCAN_BLK>>>();
    k_scatter<<<nBlkE, nThreads>>>(adj_row, adj_col, adj_val);

    // Running scale: each spmm multiplies stored values by 1/4.
    // sigma after spmm_l = 4^l; gemm_l adds bias * (1/sigma_l).
    k_spmm<128><<<spmmBlocks, nThreads>>>(Xh, Agg);
    k_gemm_h<<<gemmGrid, nThreads, GSMEM>>>(Agg, Wh1, b1, 1.f / 4.f, H, NN, 128);
    k_spmm<256><<<spmmBlocks, nThreads>>>(H, Agg);
    k_gemm_h<<<gemmGrid, nThreads, GSMEM>>>(Agg, Wh2, b2, 1.f / 16.f, H, NN, 256);
    k_spmm<256><<<spmmBlocks, nThreads>>>(H, Agg);
    k_gemm_h<<<gemmGrid, nThreads, GSMEM>>>(Agg, Wh3, b3, 1.f / 64.f, H, NN, 256);
    k_spmm<256><<<spmmBlocks, nThreads>>>(H, Agg);
    k_gemm_h<<<gemmGrid, nThreads, GSMEM>>>(Agg, Wh4, b4, 1.f / 256.f, H, NN, 256);

    int fcBlocks = (NN + 7) / 8;
    k_fc_lsm<<<fcBlocks, nThreads>>>(H, fc_w, fc_b, out);
}

// round 8
// speedup vs baseline: 2.8931x; 1.1768x over previous
#include <cuda_runtime.h>
#include <cuda_fp16.h>
#include <math.h>
#include <stdint.h>

#define NN 100000
#define EE 3200000
#define NHID 256
#define NCLASS 16
#define SCAN_BLK 1024
#define NSCANBLK ((NN + SCAN_BLK - 1) / SCAN_BLK)   // 98

// ---------------- scratch (static device globals) ---------------------------
__device__ __half g_Xh[(size_t)NN * 128];   // x in fp16
__device__ __half g_H[(size_t)NN * 256];    // GEMM output (layer act), fp16 (scaled)
__device__ __half g_Agg[(size_t)NN * 256];  // SpMM output, fp16 (scaled)
__device__ int2   g_cv[EE];                 // packed (col, val) CSR payload
__device__ int    g_rowptr[NN + 1];
__device__ int    g_cursor[NN];
__device__ int    g_blocksums[SCAN_BLK];
__device__ __half g_Wh1[256 * 128];         // weights [n][k] K-major fp16
__device__ __half g_Wh2[256 * 256];
__device__ __half g_Wh3[256 * 256];
__device__ __half g_Wh4[256 * 256];
__device__ __half g_fwT[16 * 256];          // fc_w transposed [n][k] fp16

__device__ __forceinline__ uint32_t smem_u32(const void* p) {
    uint32_t a;
    asm("{ .reg .u64 t; cvta.to.shared.u64 t, %1; cvt.u32.u64 %0, t; }"
        : "=r"(a) : "l"(p));
    return a;
}

__device__ __forceinline__ void cpasync16(uint32_t dst, const void* src) {
    asm volatile("cp.async.ca.shared.global [%0], [%1], 16;" :: "r"(dst), "l"(src));
}

// ---------------- prep: fp16 conversions -------------------------------------
// Items: [0, 32768) Wh1 | 3x65536 Wh2/3/4 | 4096 fwT | 3.2M float4 chunks of x
#define PREP_W1   (256 * 128)
#define PREP_W    (256 * 256)
#define PREP_FW   (16 * 256)
#define PREP_X4   ((long long)NN * 128 / 4)
#define PREP_TOTAL (PREP_W1 + 3LL * PREP_W + PREP_FW + PREP_X4)

__global__ void k_prep(const float* __restrict__ x,
                       const float* __restrict__ w1, const float* __restrict__ w2,
                       const float* __restrict__ w3, const float* __restrict__ w4,
                       const float* __restrict__ fcw) {
    long long i = (long long)blockIdx.x * blockDim.x + threadIdx.x;
    if (i < PREP_W1) {
        int n = (int)(i / 128), k = (int)(i % 128);
        g_Wh1[i] = __float2half_rn(w1[k * 256 + n]);
        return;
    }
    i -= PREP_W1;
    if (i < 3 * PREP_W) {
        int w = (int)(i / PREP_W);
        int r = (int)(i % PREP_W);
        int n = r / 256, k = r % 256;
        if (w == 0) g_Wh2[r] = __float2half_rn(w2[k * 256 + n]);
        else if (w == 1) g_Wh3[r] = __float2half_rn(w3[k * 256 + n]);
        else g_Wh4[r] = __float2half_rn(w4[k * 256 + n]);
        return;
    }
    i -= 3 * PREP_W;
    if (i < PREP_FW) {
        int n = (int)(i / 256), k = (int)(i % 256);
        g_fwT[i] = __float2half_rn(fcw[k * 16 + n]);
        return;
    }
    i -= PREP_FW;
    if (i < PREP_X4) {
        float4 v = ((const float4*)x)[i];
        __half2 h0 = __floats2half2_rn(v.x, v.y);
        __half2 h1 = __floats2half2_rn(v.z, v.w);
        ((uint2*)g_Xh)[i] = make_uint2(*(uint32_t*)&h0, *(uint32_t*)&h1);
    }
}

// ---------------- CSR build --------------------------------------------------
__global__ void k_zero_cnt() {
    int i = blockIdx.x * blockDim.x + threadIdx.x;
    if (i < NN) g_cursor[i] = 0;
}

__global__ void k_hist(const int* __restrict__ row) {
    int e = blockIdx.x * blockDim.x + threadIdx.x;
    if (e < EE) atomicAdd(&g_cursor[row[e]], 1);
}

__global__ void k_scan1() {
    __shared__ int s[SCAN_BLK];
    int t = threadIdx.x;
    int gid = blockIdx.x * SCAN_BLK + t;
    s[t] = (gid < NN) ? g_cursor[gid] : 0;
    for (int d = 1; d < SCAN_BLK; d <<= 1) {
        __syncthreads();
        int u = (t >= d) ? s[t - d] : 0;
        __syncthreads();
        s[t] += u;
    }
    __syncthreads();
    if (gid < NN) g_rowptr[gid + 1] = s[t];
    if (t == SCAN_BLK - 1) g_blocksums[blockIdx.x] = s[t];
}

__global__ void k_scan23() {
    __shared__ int s[128];
    int t = threadIdx.x;
    if (t < 128) s[t] = (t < NSCANBLK) ? g_blocksums[t] : 0;
    __syncthreads();
    if (t < 128) {
        for (int d = 1; d < 128; d <<= 1) {
            __syncthreads();
            int u = (t >= d) ? s[t - d] : 0;
            __syncthreads();
            s[t] += u;
        }
    } else {
        for (int d = 1; d < 128; d <<= 1) { __syncthreads(); __syncthreads(); }
    }
    __syncthreads();
    for (int i = t; i < NN; i += SCAN_BLK) {
        int b = i >> 10;
        int off = b ? s[b - 1] : 0;
        g_rowptr[i + 1] += off;
    }
    if (t == 0) g_rowptr[0] = 0;
    __syncthreads();
    for (int i = t; i < NN; i += SCAN_BLK)
        g_cursor[i] = g_rowptr[i];
}

__global__ void k_scatter(const int* __restrict__ row, const int* __restrict__ col,
                          const float* __restrict__ val) {
    int e = blockIdx.x * blockDim.x + threadIdx.x;
    if (e < EE) {
        int r = row[e];
        int p = atomicAdd(&g_cursor[r], 1);
        g_cv[p] = make_int2(col[e], __float_as_int(val[e]));
    }
}

// ---------------- SpMM (CSR, fp16 gather -> fp16 out, scaled by 1/4) --------
// One warp per dest node. NC = 128 (layer 1) or 256.
template <int NC>
__global__ void k_spmm(const __half* __restrict__ S, __half* __restrict__ out) {
    int w = (blockIdx.x * blockDim.x + threadIdx.x) >> 5;
    if (w >= NN) return;
    int lane = threadIdx.x & 31;
    constexpr int HP = NC / 32;          // halves per lane: 4 or 8

    float acc[HP];
#pragma unroll
    for (int i = 0; i < HP; i++) acc[i] = 0.f;

    int s = g_rowptr[w], e = g_rowptr[w + 1];
    for (int base = s; base < e; base += 32) {
        int idx = base + lane;
        int c = 0;
        float v = 0.f;
        if (idx < e) {
            int2 q = g_cv[idx];
            c = q.x;
            v = __int_as_float(q.y);
        }
        int m = min(32, e - base);
#pragma unroll 8
        for (int j = 0; j < 32; j++) {
            if (j >= m) break;
            int cj = __shfl_sync(0xffffffffu, c, j);
            float vj = __shfl_sync(0xffffffffu, v, j);
            if (NC == 256) {
                uint4 q = ((const uint4*)S)[(size_t)cj * 32 + lane];
                const __half2* h = (const __half2*)&q;
#pragma unroll
                for (int p = 0; p < 4; p++) {
                    float2 f = __half22float2(h[p]);
                    acc[p * 2] += vj * f.x;
                    acc[p * 2 + 1] += vj * f.y;
                }
            } else {
                uint2 q = ((const uint2*)S)[(size_t)cj * 32 + lane];
                const __half2* h = (const __half2*)&q;
#pragma unroll
                for (int p = 0; p < 2; p++) {
                    float2 f = __half22float2(h[p]);
                    acc[p * 2] += vj * f.x;
                    acc[p * 2 + 1] += vj * f.y;
                }
            }
        }
    }
    const float SC = 0.25f;
    __half2 o[HP / 2];
#pragma unroll
    for (int p = 0; p < HP / 2; p++)
        o[p] = __floats2half2_rn(acc[p * 2] * SC, acc[p * 2 + 1] * SC);
    if (NC == 256)
        ((uint4*)out)[(size_t)w * 32 + lane] = *(uint4*)o;
    else
        ((uint2*)out)[(size_t)w * 32 + lane] = *(uint2*)o;
}

// ---------------- fp16 HMMA GEMM + fused (scaled) bias + relu ----------------
#define HBK 64
#define HROW 72                        // +8 halves pad (16B)
#define HTILE_HALVES (128 * HROW)      // 9216 halves = 18432 B per tile

__global__ void __launch_bounds__(256, 2) k_gemm_h(
    const __half* __restrict__ A, const __half* __restrict__ Wt,
    const float* __restrict__ bias, float bscale,
    __half* __restrict__ C, int M, int K) {
    extern __shared__ __half sm[];
    uint32_t sb = smem_u32(sm);
    int tid = threadIdx.x;
    int wid = tid >> 5, lane = tid & 31;
    int wm = wid & 1, wn = wid >> 1;
    int gid = lane >> 2, tg = lane & 3;

    int row0 = blockIdx.x * 128;
    int col0 = blockIdx.y * 128;
    int nIter = K / HBK;

    const int aoff[2] = {0, 2 * HTILE_HALVES};
    const int boff[2] = {HTILE_HALVES, 3 * HTILE_HALVES};

    float acc[4][4][4];
#pragma unroll
    for (int i = 0; i < 4; i++)
#pragma unroll
        for (int j = 0; j < 4; j++)
#pragma unroll
            for (int k = 0; k < 4; k++) acc[i][j][k] = 0.f;

    auto stage = [&](int c, int buf) {
        int k0 = c * HBK;
        const __half* Ag = A + (size_t)row0 * K + k0;
#pragma unroll
        for (int it = 0; it < 4; it++) {
            int idx = tid + it * 256;
            int r = idx >> 3, c8 = idx & 7;
            if (row0 + r < M)
                cpasync16(sb + (uint32_t)(aoff[buf] + r * HROW) * 2 + c8 * 16,
                          Ag + (size_t)r * K + c8 * 8);
        }
        const __half* Bg = Wt + (size_t)col0 * K + k0;
#pragma unroll
        for (int it = 0; it < 4; it++) {
            int idx = tid + it * 256;
            int r = idx >> 3, c8 = idx & 7;
            cpasync16(sb + (uint32_t)(boff[buf] + r * HROW) * 2 + c8 * 16,
                      Bg + (size_t)r * K + c8 * 8);
        }
        asm volatile("cp.async.commit_group;" ::: "memory");
    };

    stage(0, 0);

    for (int c = 0; c < nIter; c++) {
        int buf = c & 1;
        if (c + 1 < nIter) {
            stage(c + 1, buf ^ 1);
            asm volatile("cp.async.wait_group 1;" ::: "memory");
        } else {
            asm volatile("cp.async.wait_group 0;" ::: "memory");
        }
        __syncthreads();

        const uint32_t* As = (const uint32_t*)(sm + aoff[buf]);
        const uint32_t* Bs = (const uint32_t*)(sm + boff[buf]);

#pragma unroll
        for (int ks = 0; ks < 4; ks++) {
            int k = ks * 16;
            uint32_t a[4][4], b[4][2];
#pragma unroll
            for (int mt = 0; mt < 4; mt++) {
                int rb = wm * 64 + mt * 16 + gid;
                int base0 = (rb * HROW + k) >> 1;
                int base1 = ((rb + 8) * HROW + k) >> 1;
                a[mt][0] = As[base0 + tg];
                a[mt][1] = As[base1 + tg];
                a[mt][2] = As[base0 + tg + 4];
                a[mt][3] = As[base1 + tg + 4];
            }
#pragma unroll
            for (int nt = 0; nt < 4; nt++) {
                int nb = wn * 32 + nt * 8 + gid;
                int base = (nb * HROW + k) >> 1;
                b[nt][0] = Bs[base + tg];
                b[nt][1] = Bs[base + tg + 4];
            }
#pragma unroll
            for (int mt = 0; mt < 4; mt++)
#pragma unroll
                for (int nt = 0; nt < 4; nt++) {
                    float* d = acc[mt][nt];
                    asm volatile(
                        "mma.sync.aligned.m16n8k16.row.col.f32.f16.f16.f32 "
                        "{%0,%1,%2,%3}, {%4,%5,%6,%7}, {%8,%9}, {%0,%1,%2,%3};"
                        : "+f"(d[0]), "+f"(d[1]), "+f"(d[2]), "+f"(d[3])
                        : "r"(a[mt][0]), "r"(a[mt][1]), "r"(a[mt][2]), "r"(a[mt][3]),
                          "r"(b[nt][0]), "r"(b[nt][1]));
                }
        }
        __syncthreads();
    }

#pragma unroll
    for (int nt = 0; nt < 4; nt++) {
        int cg = col0 + wn * 32 + nt * 8 + tg * 2;
        float bx = bias[cg] * bscale, by = bias[cg + 1] * bscale;
#pragma unroll
        for (int mt = 0; mt < 4; mt++) {
            int rg = row0 + wm * 64 + mt * 16 + gid;
            float* d = acc[mt][nt];
            if (rg < M) {
                float v0 = fmaxf(d[0] + bx, 0.f);
                float v1 = fmaxf(d[1] + by, 0.f);
                *(__half2*)(C + (size_t)rg * 256 + cg) = __floats2half2_rn(v0, v1);
            }
            if (rg + 8 < M) {
                float v2 = fmaxf(d[2] + bx, 0.f);
                float v3 = fmaxf(d[3] + by, 0.f);
                *(__half2*)(C + (size_t)(rg + 8) * 256 + cg) = __floats2half2_rn(v2, v3);
            }
        }
    }
}

// ---------------- HMMA FC + log_softmax (fp16 H at scale 1/256) --------------
// 4 warps/block, 16 rows/warp. Logits = (H @ fwT^T)*256 + fb, then log_softmax.
__global__ void __launch_bounds__(128) k_fc_hmma(const __half* __restrict__ H,
                                                 const float* __restrict__ fb,
                                                 float* __restrict__ out) {
    __shared__ float sfb[16];
    int tid = threadIdx.x;
    if (tid < 16) sfb[tid] = fb[tid];
    __syncthreads();

    int wid = tid >> 5, lane = tid & 31;
    int gid = lane >> 2, tg = lane & 3;
    int row0 = (blockIdx.x * 4 + wid) * 16;
    if (row0 >= NN) return;

    int rA = row0 + gid;
    int rB = row0 + gid + 8;
    int rAc = min(rA, NN - 1);      // clamp for safe loads
    int rBc = min(rB, NN - 1);

    float c0[4] = {0.f, 0.f, 0.f, 0.f};   // ntile0: rows gid/gid+8, n=2tg..
    float c1[4] = {0.f, 0.f, 0.f, 0.f};   // ntile1: n=8+2tg..

    const __half* HA = H + (size_t)rAc * 256;
    const __half* HB = H + (size_t)rBc * 256;
    const __half* W0 = g_fwT + (size_t)gid * 256;        // n = gid
    const __half* W1 = g_fwT + (size_t)(gid + 8) * 256;  // n = gid + 8

#pragma unroll
    for (int kc = 0; kc < 16; kc++) {
        int k = kc * 16;
        uint32_t a0 = *(const uint32_t*)(HA + k + 2 * tg);
        uint32_t a1 = *(const uint32_t*)(HB + k + 2 * tg);
        uint32_t a2 = *(const uint32_t*)(HA + k + 2 * tg + 8);
        uint32_t a3 = *(const uint32_t*)(HB + k + 2 * tg + 8);
        uint32_t b00 = *(const uint32_t*)(W0 + k + 2 * tg);
        uint32_t b01 = *(const uint32_t*)(W0 + k + 2 * tg + 8);
        uint32_t b10 = *(const uint32_t*)(W1 + k + 2 * tg);
        uint32_t b11 = *(const uint32_t*)(W1 + k + 2 * tg + 8);
        asm volatile(
            "mma.sync.aligned.m16n8k16.row.col.f32.f16.f16.f32 "
            "{%0,%1,%2,%3}, {%4,%5,%6,%7}, {%8,%9}, {%0,%1,%2,%3};"
            : "+f"(c0[0]), "+f"(c0[1]), "+f"(c0[2]), "+f"(c0[3])
            : "r"(a0), "r"(a1), "r"(a2), "r"(a3), "r"(b00), "r"(b01));
        asm volatile(
            "mma.sync.aligned.m16n8k16.row.col.f32.f16.f16.f32 "
            "{%0,%1,%2,%3}, {%4,%5,%6,%7}, {%8,%9}, {%0,%1,%2,%3};"
            : "+f"(c1[0]), "+f"(c1[1]), "+f"(c1[2]), "+f"(c1[3])
            : "r"(a0), "r"(a1), "r"(a2), "r"(a3), "r"(b10), "r"(b11));
    }

    // logits: row rA -> {c0[0],c0[1]} at n=2tg,2tg+1; {c1[0],c1[1]} at n=8+2tg..
    //         row rB -> {c0[2],c0[3]}, {c1[2],c1[3]}
    float fb0 = sfb[2 * tg], fb1 = sfb[2 * tg + 1];
    float fb2 = sfb[8 + 2 * tg], fb3 = sfb[8 + 2 * tg + 1];

#pragma unroll
    for (int rr = 0; rr < 2; rr++) {
        int row = rr ? rB : rA;
        float v0 = (rr ? c0[2] : c0[0]) * 256.f + fb0;
        float v1 = (rr ? c0[3] : c0[1]) * 256.f + fb1;
        float v2 = (rr ? c1[2] : c1[0]) * 256.f + fb2;
        float v3 = (rr ? c1[3] : c1[1]) * 256.f + fb3;
        float mx = fmaxf(fmaxf(v0, v1), fmaxf(v2, v3));
        mx = fmaxf(mx, __shfl_xor_sync(0xffffffffu, mx, 1));
        mx = fmaxf(mx, __shfl_xor_sync(0xffffffffu, mx, 2));
        float sm = expf(v0 - mx) + expf(v1 - mx) + expf(v2 - mx) + expf(v3 - mx);
        sm += __shfl_xor_sync(0xffffffffu, sm, 1);
        sm += __shfl_xor_sync(0xffffffffu, sm, 2);
        float ls = logf(sm);
        if (row < NN) {
            float* o = out + (size_t)row * 16;
            *(float2*)(o + 2 * tg) = make_float2((v0 - mx) - ls, (v1 - mx) - ls);
            *(float2*)(o + 8 + 2 * tg) = make_float2((v2 - mx) - ls, (v3 - mx) - ls);
        }
    }
}

// ---------------- launch -----------------------------------------------------
extern "C" void kernel_launch(void* const* d_in, const int* in_sizes, int n_in,
                              void* d_out, int out_size) {
    const float* x    = (const float*)d_in[0];
    const float* adj_val = (const float*)d_in[1];
    const float* w1 = (const float*)d_in[2];
    const float* b1 = (const float*)d_in[3];
    const float* w2 = (const float*)d_in[4];
    const float* b2 = (const float*)d_in[5];
    const float* w3 = (const float*)d_in[6];
    const float* b3 = (const float*)d_in[7];
    const float* w4 = (const float*)d_in[8];
    const float* b4 = (const float*)d_in[9];
    const float* fc_w = (const float*)d_in[10];
    const float* fc_b = (const float*)d_in[11];
    const int* adj_row = (const int*)d_in[12];
    const int* adj_col = (const int*)d_in[13];
    float* out = (float*)d_out;

    __half* Xh;  cudaGetSymbolAddress((void**)&Xh, g_Xh);
    __half* H;   cudaGetSymbolAddress((void**)&H, g_H);
    __half* Agg; cudaGetSymbolAddress((void**)&Agg, g_Agg);
    __half* Wh1; cudaGetSymbolAddress((void**)&Wh1, g_Wh1);
    __half* Wh2; cudaGetSymbolAddress((void**)&Wh2, g_Wh2);
    __half* Wh3; cudaGetSymbolAddress((void**)&Wh3, g_Wh3);
    __half* Wh4; cudaGetSymbolAddress((void**)&Wh4, g_Wh4);

    const int GSMEM = 4 * HTILE_HALVES * 2;   // 73728 bytes
    cudaFuncSetAttribute(k_gemm_h, cudaFuncAttributeMaxDynamicSharedMemorySize, GSMEM);

    const int nThreads = 256;
    int nBlkN = (NN + nThreads - 1) / nThreads;
    int nBlkE = (EE + nThreads - 1) / nThreads;
    int prepBlk = (int)((PREP_TOTAL + nThreads - 1) / nThreads);

    dim3 gemmGrid((NN + 127) / 128, 2);
    int spmmBlocks = (NN * 32 + nThreads - 1) / nThreads;

    k_prep<<<prepBlk, nThreads>>>(x, w1, w2, w3, w4, fc_w);
    k_zero_cnt<<<nBlkN, nThreads>>>();
    k_hist<<<nBlkE, nThreads>>>(adj_row);
    k_scan1<<<NSCANBLK, SCAN_BLK>>>();
    k_scan23<<<1, SCAN_BLK>>>();
    k_scatter<<<nBlkE, nThreads>>>(adj_row, adj_col, adj_val);

    // Running scale: each spmm multiplies stored values by 1/4 (sigma_l = 4^l).
    k_spmm<128><<<spmmBlocks, nThreads>>>(Xh, Agg);
    k_gemm_h<<<gemmGrid, nThreads, GSMEM>>>(Agg, Wh1, b1, 1.f / 4.f, H, NN, 128);
    k_spmm<256><<<spmmBlocks, nThreads>>>(H, Agg);
    k_gemm_h<<<gemmGrid, nThreads, GSMEM>>>(Agg, Wh2, b2, 1.f / 16.f, H, NN, 256);
    k_spmm<256><<<spmmBlocks, nThreads>>>(H, Agg);
    k_gemm_h<<<gemmGrid, nThreads, GSMEM>>>(Agg, Wh3, b3, 1.f / 64.f, H, NN, 256);
    k_spmm<256><<<spmmBlocks, nThreads>>>(H, Agg);
    k_gemm_h<<<gemmGrid, nThreads, GSMEM>>>(Agg, Wh4, b4, 1.f / 256.f, H, NN, 256);

    int fcBlocks = (NN + 63) / 64;
    k_fc_hmma<<<fcBlocks, 128>>>(H, fc_b, out);
}